// round 16
// baseline (speedup 1.0000x reference)
#include <cuda_runtime.h>
#include <cuda_fp16.h>
#include <math.h>
#include <stdint.h>

#define BB 4
#define SS 2048
#define EE 1024
#define FF 3072   // 3*EE

// ---------------- scratch (fp16 representations) ----------------
__device__ __half g_Xh[(size_t)BB * SS * EE];
__device__ __half g_Wh[(size_t)FF * EE];
__device__ __half g_qkv_h[(size_t)BB * SS * FF];
__device__ __half g_attn_h[(size_t)BB * SS * SS];

// ---------------- PTX helpers ----------------
__device__ __forceinline__ uint32_t smem_u32(const void* p) {
    return (uint32_t)__cvta_generic_to_shared(p);
}
__device__ __forceinline__ void cp16(uint32_t s, const void* g) {
    asm volatile("cp.async.cg.shared.global [%0], [%1], 16;\n" :: "r"(s), "l"(g));
}
__device__ __forceinline__ void cp_commit() {
    asm volatile("cp.async.commit_group;\n" ::: "memory");
}
__device__ __forceinline__ void cp_wait0() {
    asm volatile("cp.async.wait_group 0;\n" ::: "memory");
}
__device__ __forceinline__ void ldsm4(uint32_t* r, uint32_t a) {
    asm volatile("ldmatrix.sync.aligned.m8n8.x4.shared.b16 {%0,%1,%2,%3}, [%4];"
        : "=r"(r[0]), "=r"(r[1]), "=r"(r[2]), "=r"(r[3]) : "r"(a));
}
__device__ __forceinline__ void ldsm4t(uint32_t* r, uint32_t a) {
    asm volatile("ldmatrix.sync.aligned.m8n8.x4.trans.shared.b16 {%0,%1,%2,%3}, [%4];"
        : "=r"(r[0]), "=r"(r[1]), "=r"(r[2]), "=r"(r[3]) : "r"(a));
}
__device__ __forceinline__ void mma_f16(float* c, const uint32_t* a, const uint32_t* b) {
    asm volatile("mma.sync.aligned.m16n8k16.row.col.f32.f16.f16.f32 "
        "{%0,%1,%2,%3}, {%4,%5,%6,%7}, {%8,%9}, {%0,%1,%2,%3};"
        : "+f"(c[0]), "+f"(c[1]), "+f"(c[2]), "+f"(c[3])
        : "r"(a[0]), "r"(a[1]), "r"(a[2]), "r"(a[3]), "r"(b[0]), "r"(b[1]));
}

// ---------------- smem tile layout (BK = 64) ----------------
// A tile: 128 rows x 144B (128B data = 64 fp16 + 16B pad). (r*9+c) mod 8
// walks all banks -> conflict-free ldmatrix/stores.
// B tile non-trans: same as A (B stored [N][K]).
// B tile trans (native V [K][N]): 64 k-rows x 272B (256B data + 16B pad).
// 17 chunks/row, 17 mod 8 = 1 -> 8 consecutive k-rows at one n-chunk hit 8
// distinct banks: conflict-free ldmatrix.trans.
#define ROWA     144
#define ROWBT    272
#define TILE_A   18432            // 128*144
#define TILE_B0  18432
#define TILE_B1  17408            // 64*272
#define STAGE0   (TILE_A + TILE_B0)   // 36864
#define STAGE1   (TILE_A + TILE_B1)   // 35840

// 128 threads per CTA
template <int TRANSB>
__device__ __forceinline__ void load_stage(
    uint32_t sbase, const __half* gA, const __half* gB,
    int m0, int n0, int k0, int lda, int ldb, int tid)
{
    // A: 128 rows x 8 chunks = 1024 chunks over 128 threads
#pragma unroll
    for (int j = 0; j < 8; j++) {
        int ca = tid + j * 128;
        int row = ca >> 3, c = ca & 7;
        cp16(sbase + row * ROWA + c * 16,
             gA + (size_t)(m0 + row) * lda + k0 + c * 8);
    }
    if (!TRANSB) {
        // B [N][K]: 128 rows x 8 chunks
#pragma unroll
        for (int j = 0; j < 8; j++) {
            int cb = tid + j * 128;
            int row = cb >> 3, c = cb & 7;
            cp16(sbase + TILE_A + row * ROWA + c * 16,
                 gB + (size_t)(n0 + row) * ldb + k0 + c * 8);
        }
    } else {
        // B [K][N] native: 64 k-rows x 16 chunks
#pragma unroll
        for (int j = 0; j < 8; j++) {
            int cb = tid + j * 128;
            int row = cb >> 4, c = cb & 15;
            cp16(sbase + TILE_A + row * ROWBT + c * 16,
                 gB + (size_t)(k0 + row) * ldb + n0 + c * 8);
        }
    }
}

// ---------------------------------------------------------------------------
// fp16 GEMM:  C = alpha * (A @ op(B))
//   TRANSB=0: B stored [N,K] row-major (C = A @ B^T)
//   TRANSB=1: B stored [K,N] row-major (C = A @ B), via ldmatrix.trans
// A: [M,K] fp16. BK=64, 128x128 CTA tiles, 4 warps x (64x64).
// mode 0: C -> fp16 Ch, fp32 bias added first.
// mode 1: C -> fp32 Cf, scaled by alpha.
// mode 2: C -> fp16 Ch, scaled by alpha (no bias).
// 2-stage cp.async pipeline (wait_group 0; prefetch overlaps compute).
// ---------------------------------------------------------------------------
template <int TRANSB>
__global__ __launch_bounds__(128, 2) void gemm_f16(
    const __half* __restrict__ Ah, const __half* __restrict__ Bh,
    int K, int lda, int ldb, int ldc,
    size_t sA, size_t sB, size_t sC,
    int mode, float alpha,
    float* __restrict__ Cf,
    __half* __restrict__ Ch,
    const float* __restrict__ bias)
{
    extern __shared__ char dynsmem[];
    const int STAGE_B = TRANSB ? STAGE1 : STAGE0;
    const int tid  = threadIdx.x;
    const int lane = tid & 31;
    const int wid  = tid >> 5;
    const int wm   = wid & 1;   // 2 warp rows (64 each)
    const int wn   = wid >> 1;  // 2 warp cols (64 each)

    const int m0 = blockIdx.y * 128;
    const int n0 = blockIdx.x * 128;
    const int z  = blockIdx.z;

    Ah += sA * z;
    Bh += sB * z;

    // ldmatrix per-lane address components (frag maps validated R8-R14)
    const int a_row = ((lane >> 3) & 1) * 8 + (lane & 7);
    const int a_k16 = ((lane >> 4) & 1) * 16;          // bytes within 32B k-slice
    // non-trans B: frags {nt k0, nt k8, nt+1 k0, nt+1 k8}
    const int b_row = lane & 7;
    const int b_k16 = ((lane >> 3) & 1) * 16;
    const int b1_nt = (lane >> 4) & 1;
    // trans B: same frag order from native [K][N] tile
    const int bt_row = ((lane >> 3) & 1) * 8 + (lane & 7);  // k within slice
    const int bt_c   = (lane >> 4) & 1;                     // n-chunk select

    float acc[4][8][4];
#pragma unroll
    for (int mt = 0; mt < 4; mt++)
#pragma unroll
        for (int nt = 0; nt < 8; nt++)
#pragma unroll
            for (int k = 0; k < 4; k++) acc[mt][nt][k] = 0.0f;

    const uint32_t sb = smem_u32(dynsmem);
    const int KT = K >> 6;   // BK = 64

    // prologue: stage 0
    load_stage<TRANSB>(sb, Ah, Bh, m0, n0, 0, lda, ldb, tid);
    cp_commit();

    for (int kt = 0; kt < KT; kt++) {
        cp_wait0();              // load(kt) complete (only it is outstanding)
        __syncthreads();         // all warps left compute(kt-1)

        if (kt + 1 < KT) {       // prefetch overlaps compute(kt)
            load_stage<TRANSB>(sb + ((kt + 1) & 1) * STAGE_B, Ah, Bh,
                               m0, n0, (kt + 1) * 64, lda, ldb, tid);
            cp_commit();
        }

        const uint32_t base = sb + (kt & 1) * STAGE_B;
#pragma unroll
        for (int ks = 0; ks < 4; ks++) {
            uint32_t bf[4][4];   // 4 pairs cover nt = 0..7
            if (!TRANSB) {
#pragma unroll
                for (int p = 0; p < 4; p++) {
                    uint32_t ad = base + TILE_A +
                        (uint32_t)(wn * 64 + (2 * p + b1_nt) * 8 + b_row) * ROWA
                        + ks * 32 + b_k16;
                    ldsm4(bf[p], ad);
                }
            } else {
#pragma unroll
                for (int p = 0; p < 4; p++) {
                    uint32_t ad = base + TILE_A +
                        (uint32_t)(ks * 16 + bt_row) * ROWBT
                        + (uint32_t)(wn * 8 + p * 2 + bt_c) * 16;
                    ldsm4t(bf[p], ad);
                }
            }
#pragma unroll
            for (int mt = 0; mt < 4; mt++) {
                uint32_t ah[4];
                uint32_t ad = base +
                    (uint32_t)(wm * 64 + mt * 16 + a_row) * ROWA + ks * 32 + a_k16;
                ldsm4(ah, ad);
#pragma unroll
                for (int p = 0; p < 4; p++) {
                    mma_f16(acc[mt][2 * p],     ah, &bf[p][0]);
                    mma_f16(acc[mt][2 * p + 1], ah, &bf[p][2]);
                }
            }
        }
    }

    // ---- epilogue
    const int g = lane >> 2, q = lane & 3;
    const int rbase = m0 + wm * 64;
    const int cbase = n0 + wn * 64;

    if (mode == 1) {
        Cf += sC * z;
#pragma unroll
        for (int mt = 0; mt < 4; mt++) {
#pragma unroll
            for (int nt = 0; nt < 8; nt++) {
                int r = rbase + mt * 16 + g;
                int c = cbase + nt * 8 + q * 2;
                float2 v0 = make_float2(alpha * acc[mt][nt][0], alpha * acc[mt][nt][1]);
                float2 v1 = make_float2(alpha * acc[mt][nt][2], alpha * acc[mt][nt][3]);
                *reinterpret_cast<float2*>(&Cf[(size_t)r * ldc + c]) = v0;
                *reinterpret_cast<float2*>(&Cf[(size_t)(r + 8) * ldc + c]) = v1;
            }
        }
    } else if (mode == 0) {
        Ch += sC * z;
#pragma unroll
        for (int mt = 0; mt < 4; mt++) {
#pragma unroll
            for (int nt = 0; nt < 8; nt++) {
                int r = rbase + mt * 16 + g;
                int c = cbase + nt * 8 + q * 2;
                float b0 = bias[c], b1 = bias[c + 1];
#pragma unroll
                for (int hh = 0; hh < 2; hh++) {
                    float v0 = acc[mt][nt][hh * 2 + 0] + b0;
                    float v1 = acc[mt][nt][hh * 2 + 1] + b1;
                    size_t off = (size_t)(r + hh * 8) * ldc + c;
                    *reinterpret_cast<__half2*>(&Ch[off]) =
                        __halves2half2(__float2half_rn(v0), __float2half_rn(v1));
                }
            }
        }
    } else {   // mode 2: fp16, scaled
        Ch += sC * z;
#pragma unroll
        for (int mt = 0; mt < 4; mt++) {
#pragma unroll
            for (int nt = 0; nt < 8; nt++) {
                int r = rbase + mt * 16 + g;
                int c = cbase + nt * 8 + q * 2;
#pragma unroll
                for (int hh = 0; hh < 2; hh++) {
                    float v0 = alpha * acc[mt][nt][hh * 2 + 0];
                    float v1 = alpha * acc[mt][nt][hh * 2 + 1];
                    size_t off = (size_t)(r + hh * 8) * ldc + c;
                    *reinterpret_cast<__half2*>(&Ch[off]) =
                        __halves2half2(__float2half_rn(v0), __float2half_rn(v1));
                }
            }
        }
    }
}

// ---------------------------------------------------------------------------
// fp32 -> fp16, 4 elems/thread
// ---------------------------------------------------------------------------
__global__ __launch_bounds__(256) void cvt_f16(
    const float4* __restrict__ x, __half* __restrict__ hi, size_t n4)
{
    size_t i = (size_t)blockIdx.x * 256 + threadIdx.x;
    if (i >= n4) return;
    float4 v = x[i];
    *reinterpret_cast<__half2*>(&hi[i * 4]) =
        __halves2half2(__float2half_rn(v.x), __float2half_rn(v.y));
    *reinterpret_cast<__half2*>(&hi[i * 4 + 2]) =
        __halves2half2(__float2half_rn(v.z), __float2half_rn(v.w));
}

// ---------------------------------------------------------------------------
// Row softmax: reads fp16 scores (in place), writes fp32 attn + fp16 copy
// ---------------------------------------------------------------------------
__global__ __launch_bounds__(256) void softmax_h(
    __half* __restrict__ sc, float* __restrict__ attn)
{
    size_t rbase = (size_t)blockIdx.x * SS;
    __half* row = sc + rbase;
    float* orow = attn + rbase;
    __shared__ float red[256];
    const int t = threadIdx.x;

    float vals[8];
    float vmax = -INFINITY;
#pragma unroll
    for (int i = 0; i < 8; i++) {
        vals[i] = __half2float(row[t + i * 256]);
        vmax = fmaxf(vmax, vals[i]);
    }
    red[t] = vmax;
    __syncthreads();
#pragma unroll
    for (int s = 128; s > 0; s >>= 1) {
        if (t < s) red[t] = fmaxf(red[t], red[t + s]);
        __syncthreads();
    }
    vmax = red[0];
    __syncthreads();

    float sum = 0.0f;
#pragma unroll
    for (int i = 0; i < 8; i++) {
        vals[i] = __expf(vals[i] - vmax);
        sum += vals[i];
    }
    red[t] = sum;
    __syncthreads();
#pragma unroll
    for (int s = 128; s > 0; s >>= 1) {
        if (t < s) red[t] += red[t + s];
        __syncthreads();
    }
    const float inv = 1.0f / red[0];
#pragma unroll
    for (int i = 0; i < 8; i++) {
        float v = vals[i] * inv;
        int idx = t + i * 256;
        orow[idx] = v;
        row[idx] = __float2half_rn(v);
    }
}

// ---------------------------------------------------------------------------
extern "C" void kernel_launch(void* const* d_in, const int* in_sizes, int n_in,
                              void* d_out, int out_size)
{
    const float* X    = (const float*)d_in[0];  // [B,S,E]
    const float* W    = (const float*)d_in[1];  // [3E,E]
    const float* bias = (const float*)d_in[2];  // [3E]

    float* out  = (float*)d_out;                 // [B,S,E]
    float* attn = out + (size_t)BB * SS * EE;    // [B,S,S]

    __half *Xh, *Wh, *Qh, *Ath;
    cudaGetSymbolAddress((void**)&Xh, g_Xh);
    cudaGetSymbolAddress((void**)&Wh, g_Wh);
    cudaGetSymbolAddress((void**)&Qh, g_qkv_h);
    cudaGetSymbolAddress((void**)&Ath, g_attn_h);

    (void)cudaFuncSetAttribute(gemm_f16<0>,
        cudaFuncAttributeMaxDynamicSharedMemorySize, 2 * STAGE0);
    (void)cudaFuncSetAttribute(gemm_f16<1>,
        cudaFuncAttributeMaxDynamicSharedMemorySize, 2 * STAGE1);

    // 1) convert X and W to fp16
    cvt_f16<<<(BB * SS * EE / 4 + 255) / 256, 256>>>(
        (const float4*)X, Xh, (size_t)BB * SS * EE / 4);
    cvt_f16<<<(FF * EE / 4 + 255) / 256, 256>>>(
        (const float4*)W, Wh, (size_t)FF * EE / 4);

    // 2) qkv = X @ W^T + bias -> fp16  [8192,3072]
    gemm_f16<0><<<dim3(FF / 128, (BB * SS) / 128, 1), 128, 2 * STAGE0>>>(
        Xh, Wh,
        EE, EE, EE, FF,
        (size_t)0, (size_t)0, (size_t)0,
        0, 1.0f, nullptr, Qh, bias);

    // 3) scores = Q @ K^T / 32 -> fp16 scratch (mode 2)
    gemm_f16<0><<<dim3(SS / 128, SS / 128, BB), 128, 2 * STAGE0>>>(
        Qh, Qh + EE,
        EE, FF, FF, SS,
        (size_t)SS * FF, (size_t)SS * FF, (size_t)SS * SS,
        2, 1.0f / 32.0f, nullptr, Ath, nullptr);

    // 4) softmax rows: fp16 scores -> fp32 attn (d_out) + fp16 in place
    softmax_h<<<BB * SS, 256>>>(Ath, attn);

    // 5) out = attn @ V -> fp32  (V native [K][N] via ldmatrix.trans)
    gemm_f16<1><<<dim3(EE / 128, SS / 128, BB), 128, 2 * STAGE1>>>(
        Ath, Qh + 2 * EE,
        SS, SS, FF, EE,
        (size_t)SS * SS, (size_t)SS * FF, (size_t)SS * EE,
        1, 1.0f, out, nullptr, nullptr);
}

// round 17
// speedup vs baseline: 1.0526x; 1.0526x over previous
#include <cuda_runtime.h>
#include <cuda_fp16.h>
#include <math.h>
#include <stdint.h>

#define BB 4
#define SS 2048
#define EE 1024
#define FF 3072   // 3*EE

// ---------------- scratch (fp16 representations) ----------------
__device__ __half g_Xh[(size_t)BB * SS * EE];
__device__ __half g_Wh[(size_t)FF * EE];
__device__ __half g_qkv_h[(size_t)BB * SS * FF];
__device__ __half g_attn_h[(size_t)BB * SS * SS];

// ---------------- PTX helpers ----------------
__device__ __forceinline__ uint32_t smem_u32(const void* p) {
    return (uint32_t)__cvta_generic_to_shared(p);
}
__device__ __forceinline__ void cp16(uint32_t s, const void* g) {
    asm volatile("cp.async.cg.shared.global [%0], [%1], 16;\n" :: "r"(s), "l"(g));
}
__device__ __forceinline__ void cp_commit() {
    asm volatile("cp.async.commit_group;\n" ::: "memory");
}
__device__ __forceinline__ void cp_wait0() {
    asm volatile("cp.async.wait_group 0;\n" ::: "memory");
}
__device__ __forceinline__ void ldsm4(uint32_t* r, uint32_t a) {
    asm volatile("ldmatrix.sync.aligned.m8n8.x4.shared.b16 {%0,%1,%2,%3}, [%4];"
        : "=r"(r[0]), "=r"(r[1]), "=r"(r[2]), "=r"(r[3]) : "r"(a));
}
__device__ __forceinline__ void ldsm4t(uint32_t* r, uint32_t a) {
    asm volatile("ldmatrix.sync.aligned.m8n8.x4.trans.shared.b16 {%0,%1,%2,%3}, [%4];"
        : "=r"(r[0]), "=r"(r[1]), "=r"(r[2]), "=r"(r[3]) : "r"(a));
}
__device__ __forceinline__ void mma_f16(float* c, const uint32_t* a, const uint32_t* b) {
    asm volatile("mma.sync.aligned.m16n8k16.row.col.f32.f16.f16.f32 "
        "{%0,%1,%2,%3}, {%4,%5,%6,%7}, {%8,%9}, {%0,%1,%2,%3};"
        : "+f"(c[0]), "+f"(c[1]), "+f"(c[2]), "+f"(c[3])
        : "r"(a[0]), "r"(a[1]), "r"(a[2]), "r"(a[3]), "r"(b[0]), "r"(b[1]));
}

// ---------------- smem tile layout (BK = 64) ----------------
// A tile: 128 rows x 144B (128B data = 64 fp16 + 16B pad). (r*9+c) mod 8
// walks all banks -> conflict-free ldmatrix/stores.
// B tile non-trans: same as A (B stored [N][K]).
// B tile trans (native V [K][N]): 64 k-rows x 272B (256B data + 16B pad).
// 17 chunks/row, 17 mod 8 = 1 -> 8 consecutive k-rows at one n-chunk hit 8
// distinct banks: conflict-free ldmatrix.trans.
#define ROWA     144
#define ROWBT    272
#define TILE_A   18432            // 128*144
#define TILE_B0  18432
#define TILE_B1  17408            // 64*272
#define STAGE0   (TILE_A + TILE_B0)   // 36864
#define STAGE1   (TILE_A + TILE_B1)   // 35840

// 256 threads per CTA
template <int TRANSB>
__device__ __forceinline__ void load_stage(
    uint32_t sbase, const __half* gA, const __half* gB,
    int m0, int n0, int k0, int lda, int ldb, int tid)
{
    // A: 128 rows x 8 chunks = 1024 chunks over 256 threads
#pragma unroll
    for (int j = 0; j < 4; j++) {
        int ca = tid + j * 256;
        int row = ca >> 3, c = ca & 7;
        cp16(sbase + row * ROWA + c * 16,
             gA + (size_t)(m0 + row) * lda + k0 + c * 8);
    }
    if (!TRANSB) {
        // B [N][K]: 128 rows x 8 chunks
#pragma unroll
        for (int j = 0; j < 4; j++) {
            int cb = tid + j * 256;
            int row = cb >> 3, c = cb & 7;
            cp16(sbase + TILE_A + row * ROWA + c * 16,
                 gB + (size_t)(n0 + row) * ldb + k0 + c * 8);
        }
    } else {
        // B [K][N] native: 64 k-rows x 16 chunks
#pragma unroll
        for (int j = 0; j < 4; j++) {
            int cb = tid + j * 256;
            int row = cb >> 4, c = cb & 15;
            cp16(sbase + TILE_A + row * ROWBT + c * 16,
                 gB + (size_t)(k0 + row) * ldb + n0 + c * 8);
        }
    }
}

// ---------------------------------------------------------------------------
// fp16 GEMM:  C = alpha * (A @ op(B))
//   TRANSB=0: B stored [N,K] row-major (C = A @ B^T)
//   TRANSB=1: B stored [K,N] row-major (C = A @ B), via ldmatrix.trans
// A: [M,K] fp16. BK=64, 128x128 CTA tiles, 8 warps x (64x32).
// mode 0: C -> fp16 Ch, fp32 bias added first.
// mode 1: C -> fp32 Cf, scaled by alpha.
// mode 2: C -> fp16 Ch, scaled by alpha (no bias).
// 2-stage cp.async pipeline (wait_group 0; prefetch overlaps compute).
// ---------------------------------------------------------------------------
template <int TRANSB>
__global__ __launch_bounds__(256, 2) void gemm_f16(
    const __half* __restrict__ Ah, const __half* __restrict__ Bh,
    int K, int lda, int ldb, int ldc,
    size_t sA, size_t sB, size_t sC,
    int mode, float alpha,
    float* __restrict__ Cf,
    __half* __restrict__ Ch,
    const float* __restrict__ bias)
{
    extern __shared__ char dynsmem[];
    const int STAGE_B = TRANSB ? STAGE1 : STAGE0;
    const int tid  = threadIdx.x;
    const int lane = tid & 31;
    const int wid  = tid >> 5;
    const int wm   = wid & 1;   // 2 warp rows (64 each)
    const int wn   = wid >> 1;  // 4 warp cols (32 each)

    const int m0 = blockIdx.y * 128;
    const int n0 = blockIdx.x * 128;
    const int z  = blockIdx.z;

    Ah += sA * z;
    Bh += sB * z;

    // ldmatrix per-lane address components (frag maps validated R8-R16)
    const int a_row = ((lane >> 3) & 1) * 8 + (lane & 7);
    const int a_k16 = ((lane >> 4) & 1) * 16;          // bytes within 32B k-slice
    // non-trans B: frags {nt k0, nt k8, nt+1 k0, nt+1 k8}
    const int b_row = lane & 7;
    const int b_k16 = ((lane >> 3) & 1) * 16;
    const int b1_nt = (lane >> 4) & 1;
    // trans B: same frag order from native [K][N] tile
    const int bt_row = ((lane >> 3) & 1) * 8 + (lane & 7);  // k within slice
    const int bt_c   = (lane >> 4) & 1;                     // n-chunk select

    float acc[4][4][4];
#pragma unroll
    for (int mt = 0; mt < 4; mt++)
#pragma unroll
        for (int nt = 0; nt < 4; nt++)
#pragma unroll
            for (int k = 0; k < 4; k++) acc[mt][nt][k] = 0.0f;

    const uint32_t sb = smem_u32(dynsmem);
    const int KT = K >> 6;   // BK = 64

    // prologue: stage 0
    load_stage<TRANSB>(sb, Ah, Bh, m0, n0, 0, lda, ldb, tid);
    cp_commit();

    for (int kt = 0; kt < KT; kt++) {
        cp_wait0();              // load(kt) complete (only it is outstanding)
        __syncthreads();         // all warps left compute(kt-1)

        if (kt + 1 < KT) {       // prefetch overlaps compute(kt)
            load_stage<TRANSB>(sb + ((kt + 1) & 1) * STAGE_B, Ah, Bh,
                               m0, n0, (kt + 1) * 64, lda, ldb, tid);
            cp_commit();
        }

        const uint32_t base = sb + (kt & 1) * STAGE_B;
#pragma unroll
        for (int ks = 0; ks < 4; ks++) {
            uint32_t bf[2][4];   // 2 pairs cover nt = 0..3
            if (!TRANSB) {
#pragma unroll
                for (int p = 0; p < 2; p++) {
                    uint32_t ad = base + TILE_A +
                        (uint32_t)(wn * 32 + (2 * p + b1_nt) * 8 + b_row) * ROWA
                        + ks * 32 + b_k16;
                    ldsm4(bf[p], ad);
                }
            } else {
#pragma unroll
                for (int p = 0; p < 2; p++) {
                    uint32_t ad = base + TILE_A +
                        (uint32_t)(ks * 16 + bt_row) * ROWBT
                        + (uint32_t)(wn * 4 + p * 2 + bt_c) * 16;
                    ldsm4t(bf[p], ad);
                }
            }
#pragma unroll
            for (int mt = 0; mt < 4; mt++) {
                uint32_t ah[4];
                uint32_t ad = base +
                    (uint32_t)(wm * 64 + mt * 16 + a_row) * ROWA + ks * 32 + a_k16;
                ldsm4(ah, ad);
#pragma unroll
                for (int p = 0; p < 2; p++) {
                    mma_f16(acc[mt][2 * p],     ah, &bf[p][0]);
                    mma_f16(acc[mt][2 * p + 1], ah, &bf[p][2]);
                }
            }
        }
    }

    // ---- epilogue
    const int g = lane >> 2, q = lane & 3;
    const int rbase = m0 + wm * 64;
    const int cbase = n0 + wn * 32;

    if (mode == 1) {
        Cf += sC * z;
#pragma unroll
        for (int mt = 0; mt < 4; mt++) {
#pragma unroll
            for (int nt = 0; nt < 4; nt++) {
                int r = rbase + mt * 16 + g;
                int c = cbase + nt * 8 + q * 2;
                float2 v0 = make_float2(alpha * acc[mt][nt][0], alpha * acc[mt][nt][1]);
                float2 v1 = make_float2(alpha * acc[mt][nt][2], alpha * acc[mt][nt][3]);
                *reinterpret_cast<float2*>(&Cf[(size_t)r * ldc + c]) = v0;
                *reinterpret_cast<float2*>(&Cf[(size_t)(r + 8) * ldc + c]) = v1;
            }
        }
    } else if (mode == 0) {
        Ch += sC * z;
#pragma unroll
        for (int mt = 0; mt < 4; mt++) {
#pragma unroll
            for (int nt = 0; nt < 4; nt++) {
                int r = rbase + mt * 16 + g;
                int c = cbase + nt * 8 + q * 2;
                float b0 = bias[c], b1 = bias[c + 1];
#pragma unroll
                for (int hh = 0; hh < 2; hh++) {
                    float v0 = acc[mt][nt][hh * 2 + 0] + b0;
                    float v1 = acc[mt][nt][hh * 2 + 1] + b1;
                    size_t off = (size_t)(r + hh * 8) * ldc + c;
                    *reinterpret_cast<__half2*>(&Ch[off]) =
                        __halves2half2(__float2half_rn(v0), __float2half_rn(v1));
                }
            }
        }
    } else {   // mode 2: fp16, scaled
        Ch += sC * z;
#pragma unroll
        for (int mt = 0; mt < 4; mt++) {
#pragma unroll
            for (int nt = 0; nt < 4; nt++) {
                int r = rbase + mt * 16 + g;
                int c = cbase + nt * 8 + q * 2;
#pragma unroll
                for (int hh = 0; hh < 2; hh++) {
                    float v0 = alpha * acc[mt][nt][hh * 2 + 0];
                    float v1 = alpha * acc[mt][nt][hh * 2 + 1];
                    size_t off = (size_t)(r + hh * 8) * ldc + c;
                    *reinterpret_cast<__half2*>(&Ch[off]) =
                        __halves2half2(__float2half_rn(v0), __float2half_rn(v1));
                }
            }
        }
    }
}

// ---------------------------------------------------------------------------
// fp32 -> fp16, 4 elems/thread
// ---------------------------------------------------------------------------
__global__ __launch_bounds__(256) void cvt_f16(
    const float4* __restrict__ x, __half* __restrict__ hi, size_t n4)
{
    size_t i = (size_t)blockIdx.x * 256 + threadIdx.x;
    if (i >= n4) return;
    float4 v = x[i];
    *reinterpret_cast<__half2*>(&hi[i * 4]) =
        __halves2half2(__float2half_rn(v.x), __float2half_rn(v.y));
    *reinterpret_cast<__half2*>(&hi[i * 4 + 2]) =
        __halves2half2(__float2half_rn(v.z), __float2half_rn(v.w));
}

// ---------------------------------------------------------------------------
// Row softmax: reads fp16 scores (in place), writes fp32 attn + fp16 copy
// ---------------------------------------------------------------------------
__global__ __launch_bounds__(256) void softmax_h(
    __half* __restrict__ sc, float* __restrict__ attn)
{
    size_t rbase = (size_t)blockIdx.x * SS;
    __half* row = sc + rbase;
    float* orow = attn + rbase;
    __shared__ float red[256];
    const int t = threadIdx.x;

    float vals[8];
    float vmax = -INFINITY;
#pragma unroll
    for (int i = 0; i < 8; i++) {
        vals[i] = __half2float(row[t + i * 256]);
        vmax = fmaxf(vmax, vals[i]);
    }
    red[t] = vmax;
    __syncthreads();
#pragma unroll
    for (int s = 128; s > 0; s >>= 1) {
        if (t < s) red[t] = fmaxf(red[t], red[t + s]);
        __syncthreads();
    }
    vmax = red[0];
    __syncthreads();

    float sum = 0.0f;
#pragma unroll
    for (int i = 0; i < 8; i++) {
        vals[i] = __expf(vals[i] - vmax);
        sum += vals[i];
    }
    red[t] = sum;
    __syncthreads();
#pragma unroll
    for (int s = 128; s > 0; s >>= 1) {
        if (t < s) red[t] += red[t + s];
        __syncthreads();
    }
    const float inv = 1.0f / red[0];
#pragma unroll
    for (int i = 0; i < 8; i++) {
        float v = vals[i] * inv;
        int idx = t + i * 256;
        orow[idx] = v;
        row[idx] = __float2half_rn(v);
    }
}

// ---------------------------------------------------------------------------
extern "C" void kernel_launch(void* const* d_in, const int* in_sizes, int n_in,
                              void* d_out, int out_size)
{
    const float* X    = (const float*)d_in[0];  // [B,S,E]
    const float* W    = (const float*)d_in[1];  // [3E,E]
    const float* bias = (const float*)d_in[2];  // [3E]

    float* out  = (float*)d_out;                 // [B,S,E]
    float* attn = out + (size_t)BB * SS * EE;    // [B,S,S]

    __half *Xh, *Wh, *Qh, *Ath;
    cudaGetSymbolAddress((void**)&Xh, g_Xh);
    cudaGetSymbolAddress((void**)&Wh, g_Wh);
    cudaGetSymbolAddress((void**)&Qh, g_qkv_h);
    cudaGetSymbolAddress((void**)&Ath, g_attn_h);

    (void)cudaFuncSetAttribute(gemm_f16<0>,
        cudaFuncAttributeMaxDynamicSharedMemorySize, 2 * STAGE0);
    (void)cudaFuncSetAttribute(gemm_f16<1>,
        cudaFuncAttributeMaxDynamicSharedMemorySize, 2 * STAGE1);

    // 1) convert X and W to fp16
    cvt_f16<<<(BB * SS * EE / 4 + 255) / 256, 256>>>(
        (const float4*)X, Xh, (size_t)BB * SS * EE / 4);
    cvt_f16<<<(FF * EE / 4 + 255) / 256, 256>>>(
        (const float4*)W, Wh, (size_t)FF * EE / 4);

    // 2) qkv = X @ W^T + bias -> fp16  [8192,3072]
    gemm_f16<0><<<dim3(FF / 128, (BB * SS) / 128, 1), 256, 2 * STAGE0>>>(
        Xh, Wh,
        EE, EE, EE, FF,
        (size_t)0, (size_t)0, (size_t)0,
        0, 1.0f, nullptr, Qh, bias);

    // 3) scores = Q @ K^T / 32 -> fp16 scratch (mode 2)
    gemm_f16<0><<<dim3(SS / 128, SS / 128, BB), 256, 2 * STAGE0>>>(
        Qh, Qh + EE,
        EE, FF, FF, SS,
        (size_t)SS * FF, (size_t)SS * FF, (size_t)SS * SS,
        2, 1.0f / 32.0f, nullptr, Ath, nullptr);

    // 4) softmax rows: fp16 scores -> fp32 attn (d_out) + fp16 in place
    softmax_h<<<BB * SS, 256>>>(Ath, attn);

    // 5) out = attn @ V -> fp32  (V native [K][N] via ldmatrix.trans)
    gemm_f16<1><<<dim3(EE / 128, SS / 128, BB), 256, 2 * STAGE1>>>(
        Ath, Qh + 2 * EE,
        SS, SS, FF, EE,
        (size_t)SS * SS, (size_t)SS * FF, (size_t)SS * EE,
        1, 1.0f, out, nullptr, nullptr);
}